// round 13
// baseline (speedup 1.0000x reference)
#include <cuda_runtime.h>

// Online Normalization forward (v13 = v8 shape + work-stealing + affinity).
// x: [B=32, H=64, W=64, C=256] channels-last, fp32.
//
// 256 CTAs x 512 threads (2 CTAs/SM co-resident: best streaming bandwidth of
// all variants), work-stealing over 512 tiles of 256 rows to remove the v8
// imbalance. Each CTA records the tiles it grabbed in pass 1 and normalizes
// exactly those tiles in pass 3 (LIFO) -> L1/L2 recency preserved.
// Phases stay pure (reads | barrier | fold | barrier | scan | writes).
// Ticket counter is monotonic and replay-exact: 512 + 256 grabs per launch.

#define AFWD 0.999f
#define EPS  1e-5f

constexpr int Bn   = 32;
constexpr int HW   = 64 * 64;        // 4096 rows per batch
constexpr int Cc   = 256;
constexpr int C4   = Cc / 4;         // 64
constexpr int NCTA = 256;
constexpr int TPB  = 512;
constexpr int TR   = 256;            // rows per tile
constexpr int NT   = Bn * HW / TR;   // 512 tiles (16 per batch)
constexpr int RG   = TPB / C4;       // 8 row groups
constexpr int ITER = TR / RG;        // 32 rows per thread per tile
constexpr unsigned long long EP = NT + NCTA;   // 768 grabs per launch
constexpr int MAXT = 128;            // recorded-tile bound (avg is 2)

__device__ float g_ps[NT * Cc];      // per-tile partial sums
__device__ float g_pq[NT * Cc];
__device__ float g_bs[Bn * Cc];      // folded per-batch sums
__device__ float g_bq[Bn * Cc];
__device__ unsigned long long g_bar;   // monotonic across graph replays
__device__ unsigned long long g_tick;  // monotonic ticket counter

// Dynamic smem (floats), phase-unioned:
//   pass 1:  red_s [0:2048)  red_q [2048:4096)
//   scan:    st_s  [0:8192)  st_q  [8192:16384)   (in-place -> mu, rs)
constexpr int SMEM_FLOATS = 16384;   // 64 KB  (x2 CTA/SM = 128 KB <= 228 KB)

__device__ __forceinline__ void grid_barrier() {
    __syncthreads();
    if (threadIdx.x == 0) {
        __threadfence();
        unsigned long long t = atomicAdd(&g_bar, 1ULL) + 1ULL;
        unsigned long long target = ((t + NCTA - 1ULL) / NCTA) * NCTA;
        while (*((volatile unsigned long long*)&g_bar) < target) { }
        __threadfence();
    }
    __syncthreads();
}

__global__ __launch_bounds__(TPB, 2)
void onorm_steal(const float4* __restrict__ x4,
                 float4* __restrict__ o4,
                 const float* __restrict__ mu0,
                 const float* __restrict__ var0) {
    extern __shared__ float sm[];
    float* red_s = sm;                 // 2048 floats (pass 1)
    float* red_q = sm + 2048;          // 2048 floats
    float* st_s  = sm;                 // 8192 floats (after barriers)
    float* st_q  = sm + 8192;          // 8192 floats
    __shared__ int s_tiles[MAXT];
    __shared__ unsigned long long s_tk;

    const int tid = threadIdx.x;
    const int c4  = tid & 63;          // float4 channel index
    const int rg  = tid >> 6;          // 0..7 row group

    // ---------------- Pass 1: work-stealing stats over 512 tiles --------------
    if (tid == 0) s_tk = atomicAdd(&g_tick, 1ULL);
    __syncthreads();
    unsigned long long tk = s_tk;
    const unsigned long long ebase = (tk / EP) * EP;
    const unsigned long long eend  = ebase + (unsigned long long)NT;

    int n = 0;
    while (tk < eend && n < MAXT) {
        const int tile = (int)(tk - ebase);
        if (tid == 0) s_tiles[n] = tile;
        n++;
        const float4* p = x4 + ((size_t)tile * TR + rg) * C4 + c4;
        float4 a = {0.f,0.f,0.f,0.f}, q = {0.f,0.f,0.f,0.f};
        #pragma unroll 8
        for (int i = 0; i < ITER; i++) {
            float4 v = p[(size_t)i * RG * C4];
            a.x += v.x; a.y += v.y; a.z += v.z; a.w += v.w;
            q.x = fmaf(v.x, v.x, q.x); q.y = fmaf(v.y, v.y, q.y);
            q.z = fmaf(v.z, v.z, q.z); q.w = fmaf(v.w, v.w, q.w);
        }
        ((float4*)red_s)[rg * 64 + c4] = a;
        ((float4*)red_q)[rg * 64 + c4] = q;
        __syncthreads();
        if (tid < 64) {
            float4 sa = {0.f,0.f,0.f,0.f}, sq = {0.f,0.f,0.f,0.f};
            #pragma unroll
            for (int j = 0; j < RG; j++) {
                float4 va = ((float4*)red_s)[j * 64 + tid];
                float4 vq = ((float4*)red_q)[j * 64 + tid];
                sa.x += va.x; sa.y += va.y; sa.z += va.z; sa.w += va.w;
                sq.x += vq.x; sq.y += vq.y; sq.z += vq.z; sq.w += vq.w;
            }
            ((float4*)g_ps)[tile * 64 + tid] = sa;
            ((float4*)g_pq)[tile * 64 + tid] = sq;
        }
        __syncthreads();
        if (tid == 0) s_tk = atomicAdd(&g_tick, 1ULL);
        __syncthreads();
        tk = s_tk;
    }

    grid_barrier();     // all tile partials visible

    // ---- Fold: 8192 (batch,channel) pairs spread over 256 CTAs (32 each) -----
    if (tid < 32) {
        const int pair = blockIdx.x * 32 + tid;
        const int b = pair >> 8, c = pair & 255;
        const int base = (b * 16) * Cc + c;
        float ss = 0.f, qq = 0.f;
        #pragma unroll
        for (int k = 0; k < 16; k++) {
            ss += g_ps[base + k * Cc];
            qq += g_pq[base + k * Cc];
        }
        g_bs[pair] = ss;
        g_bq[pair] = qq;
    }

    grid_barrier();     // folded batch sums visible

    // ---- Scan: bulk smem load + in-place 32-step EMA recurrence --------------
    for (int i = tid; i < Bn * Cc; i += TPB) {
        st_s[i] = g_bs[i];
        st_q[i] = g_bq[i];
    }
    __syncthreads();
    if (tid < Cc) {
        const int c = tid;
        float mu  = mu0[c];
        float var = var0[c];
        const float inv = 1.0f / (float)HW;
        #pragma unroll
        for (int b = 0; b < Bn; b++) {
            const float s  = st_s[b * Cc + c];
            const float s2 = st_q[b * Cc + c];
            st_s[b * Cc + c] = mu;                 // in-place: becomes mu table
            st_q[b * Cc + c] = rsqrtf(var + EPS);  // in-place: becomes rs table
            const float mean = s * inv;
            const float vart = fmaf(-mean, mean, s2 * inv);
            const float d    = mean - mu;
            var = AFWD * var + (1.0f - AFWD) * vart
                + AFWD * (1.0f - AFWD) * d * d;
            mu  = fmaf(1.0f - AFWD, d, mu);
        }
    }
    __syncthreads();

    // ---------------- Pass 3: normalize own grabbed tiles (LIFO) --------------
    for (int k = n - 1; k >= 0; k--) {
        const int tile = s_tiles[k];
        const int b    = tile >> 4;            // 16 tiles per batch
        const float4 m = ((const float4*)st_s)[b * 64 + c4];
        const float4 r = ((const float4*)st_q)[b * 64 + c4];
        const size_t tb = ((size_t)tile * TR + rg) * C4 + c4;
        #pragma unroll 8
        for (int i = ITER - 1; i >= 0; i--) {
            float4 v = x4[tb + (size_t)i * RG * C4];
            float4 w;
            w.x = (v.x - m.x) * r.x;
            w.y = (v.y - m.y) * r.y;
            w.z = (v.z - m.z) * r.z;
            w.w = (v.w - m.w) * r.w;
            __stcs(&o4[tb + (size_t)i * RG * C4], w);
        }
    }
}

extern "C" void kernel_launch(void* const* d_in, const int* in_sizes, int n_in,
                              void* d_out, int out_size) {
    const float* x    = (const float*)d_in[0];
    const float* mu0  = (const float*)d_in[1];
    const float* var0 = (const float*)d_in[2];
    float* out = (float*)d_out;

    static bool attr_set = false;
    if (!attr_set) {
        cudaFuncSetAttribute(onorm_steal,
                             cudaFuncAttributeMaxDynamicSharedMemorySize,
                             SMEM_FLOATS * sizeof(float));
        attr_set = true;
    }

    onorm_steal<<<NCTA, TPB, SMEM_FLOATS * sizeof(float)>>>(
        (const float4*)x, (float4*)out, mu0, var0);
}

// round 14
// speedup vs baseline: 1.0930x; 1.0930x over previous
#include <cuda_runtime.h>

// Online Normalization forward, fused persistent kernel (v14 = v4 micro-tuned).
// x: [B=32, H=64, W=64, C=256] channels-last, fp32.
//
// Structure identical to v4 (champion): 128 CTAs x 1024 threads (1/SM,
// co-resident), CTA (t*4+q) owns quarter q of batch t (1 MB). Pass 1:
// sync-free register accumulation (unroll 16 for a wider front-batched load
// window). One grid barrier. Per-CTA EMA scan to its own batch. Pass 3:
// reverse-order re-read of own chunk (L1/L2 hits), write-through streaming
// stores (__stwt) to keep the output out of L2 entirely.

#define AFWD 0.999f
#define EPS  1e-5f

constexpr int Bn   = 32;
constexpr int HW   = 64 * 64;       // 4096 rows per batch
constexpr int Cc   = 256;
constexpr int C4   = Cc / 4;        // 64
constexpr int NCTA = 128;           // 32 batches x 4 quarters
constexpr int TPB  = 1024;
constexpr int ROWS = HW / 4;        // 1024 rows per CTA
constexpr int ITER = ROWS / 16;     // 64 rows per thread (16 row-groups)

__device__ float g_psum[Bn * 4 * Cc];
__device__ float g_psq [Bn * 4 * Cc];
__device__ unsigned long long g_bar;   // monotonic across graph replays

__device__ __forceinline__ void grid_barrier() {
    __syncthreads();
    if (threadIdx.x == 0) {
        __threadfence();
        unsigned long long t = atomicAdd(&g_bar, 1ULL) + 1ULL;
        unsigned long long target = ((t + NCTA - 1ULL) / NCTA) * NCTA;
        while (*((volatile unsigned long long*)&g_bar) < target) { }
        __threadfence();
    }
    __syncthreads();
}

__global__ __launch_bounds__(TPB, 1)
void onorm_fused(const float4* __restrict__ x4,
                 float4* __restrict__ o4,
                 const float* __restrict__ mu0,
                 const float* __restrict__ var0) {
    __shared__ float red_s[4096];
    __shared__ float red_q[4096];
    __shared__ float sm_mu[Cc];
    __shared__ float sm_rs[Cc];

    const int tid = threadIdx.x;
    const int cta = blockIdx.x;
    const int c4  = tid & 63;          // float4 channel index
    const int rg  = tid >> 6;          // 0..15 row group
    const int t   = cta >> 2;          // batch owned by this CTA
    const int qq  = cta & 3;           // quarter of the batch

    const size_t base = ((size_t)t * HW + (size_t)qq * ROWS + rg) * C4 + c4;
    const float4* p = x4 + base;

    // ---------------- Pass 1: sync-free streaming accumulation ----------------
    float4 a = {0.f,0.f,0.f,0.f}, q = {0.f,0.f,0.f,0.f};
    #pragma unroll 16
    for (int i = 0; i < ITER; i++) {
        float4 v = p[(size_t)i * 16 * C4];
        a.x += v.x; a.y += v.y; a.z += v.z; a.w += v.w;
        q.x = fmaf(v.x, v.x, q.x); q.y = fmaf(v.y, v.y, q.y);
        q.z = fmaf(v.z, v.z, q.z); q.w = fmaf(v.w, v.w, q.w);
    }
    ((float4*)red_s)[rg * 64 + c4] = a;
    ((float4*)red_q)[rg * 64 + c4] = q;
    __syncthreads();
    if (tid < 64) {
        float4 sa = {0.f,0.f,0.f,0.f}, sq = {0.f,0.f,0.f,0.f};
        #pragma unroll
        for (int j = 0; j < 16; j++) {
            float4 va = ((float4*)red_s)[j * 64 + tid];
            float4 vq = ((float4*)red_q)[j * 64 + tid];
            sa.x += va.x; sa.y += va.y; sa.z += va.z; sa.w += va.w;
            sq.x += vq.x; sq.y += vq.y; sq.z += vq.z; sq.w += vq.w;
        }
        ((float4*)g_psum)[cta * 64 + tid] = sa;
        ((float4*)g_psq )[cta * 64 + tid] = sq;
    }

    grid_barrier();

    // ------------- Scan (per-CTA, up to own batch, from L2) -------------------
    if (tid < Cc) {
        const int c = tid;
        float mu  = mu0[c];
        float var = var0[c];
        const float inv = 1.0f / (float)HW;
        for (int tt = 0; tt < t; tt++) {
            float s  = g_psum[(tt * 4 + 0) * Cc + c] + g_psum[(tt * 4 + 1) * Cc + c]
                     + g_psum[(tt * 4 + 2) * Cc + c] + g_psum[(tt * 4 + 3) * Cc + c];
            float s2 = g_psq [(tt * 4 + 0) * Cc + c] + g_psq [(tt * 4 + 1) * Cc + c]
                     + g_psq [(tt * 4 + 2) * Cc + c] + g_psq [(tt * 4 + 3) * Cc + c];
            const float mean = s * inv;
            const float vart = fmaf(-mean, mean, s2 * inv);
            const float d    = mean - mu;
            var = AFWD * var + (1.0f - AFWD) * vart
                + AFWD * (1.0f - AFWD) * d * d;
            mu  = fmaf(1.0f - AFWD, d, mu);
        }
        sm_mu[c] = mu;
        sm_rs[c] = rsqrtf(var + EPS);
    }
    __syncthreads();

    // ---------------- Pass 3: normalize own chunk (reverse order) -------------
    const float4 m = ((const float4*)sm_mu)[c4];
    const float4 r = ((const float4*)sm_rs)[c4];
    float4* o = o4 + base;
    #pragma unroll 16
    for (int i = ITER - 1; i >= 0; i--) {
        float4 v = p[(size_t)i * 16 * C4];
        float4 w;
        w.x = (v.x - m.x) * r.x;
        w.y = (v.y - m.y) * r.y;
        w.z = (v.z - m.z) * r.z;
        w.w = (v.w - m.w) * r.w;
        __stwt(&o[(size_t)i * 16 * C4], w);
    }
}

extern "C" void kernel_launch(void* const* d_in, const int* in_sizes, int n_in,
                              void* d_out, int out_size) {
    const float* x    = (const float*)d_in[0];
    const float* mu0  = (const float*)d_in[1];
    const float* var0 = (const float*)d_in[2];
    float* out = (float*)d_out;

    onorm_fused<<<NCTA, TPB>>>((const float4*)x, (float4*)out, mu0, var0);
}